// round 1
// baseline (speedup 1.0000x reference)
#include <cuda_runtime.h>
#include <cuda_bf16.h>
#include <cstdint>

#define UNITS 256
#define NUM_BUCKETS 501
#define LB (-17.0f)
#define STEPF 0.05f
#define INV_STEP 20.0f
#define RESIDUE (-17.05f)

// Precomputed table: per (unit, bucket):
//   .x = STEP * csum_exc[u][j] + RESIDUE + b[u]
//   .y = w[u][j] = relu(v[u][j])
__device__ float2 g_tab[UNITS * NUM_BUCKETS];

// ---------------------------------------------------------------------------
// Kernel A: build the per-(unit,bucket) table. One block per unit.
// 512 threads: Hillis-Steele inclusive scan over 501 relu'd weights.
// ---------------------------------------------------------------------------
__global__ void build_table_kernel(const float* __restrict__ v,
                                   const float* __restrict__ b) {
    __shared__ float s[512];
    const int u = blockIdx.x;
    const int t = threadIdx.x;

    float w = 0.0f;
    if (t < NUM_BUCKETS) {
        w = fmaxf(v[u * NUM_BUCKETS + t], 0.0f);
    }
    s[t] = w;

    // inclusive scan
    #pragma unroll
    for (int off = 1; off < 512; off <<= 1) {
        __syncthreads();
        float add = (t >= off) ? s[t - off] : 0.0f;
        __syncthreads();
        s[t] += add;
    }
    __syncthreads();

    if (t < NUM_BUCKETS) {
        float inc = s[t];
        float exc = inc - w;           // exclusive cumsum
        float2 e;
        e.x = STEPF * exc + RESIDUE + b[u];
        e.y = w;
        g_tab[u * NUM_BUCKETS + t] = e;
    }
}

// ---------------------------------------------------------------------------
// Kernel B: per-element bucket lookup + sigmoid. float4 vectorized.
// Each thread handles 4 consecutive units of one batch row.
// ---------------------------------------------------------------------------
__global__ void __launch_bounds__(256)
iso_main_kernel(const float4* __restrict__ x4,
                float4* __restrict__ out4,
                int nvec) {
    int i = blockIdx.x * blockDim.x + threadIdx.x;
    if (i >= nvec) return;

    float4 xv = x4[i];
    // UNITS/4 = 64 vectors per row; column group = i & 63
    const int ubase = (i & 63) * 4;

    float xin[4] = {xv.x, xv.y, xv.z, xv.w};
    float oo[4];

    #pragma unroll
    for (int j = 0; j < 4; ++j) {
        const int u = ubase + j;
        float xc = fminf(fmaxf(xin[j], LB + 1e-9f), 8.0f - 1e-9f);
        float f = (xc - LB + STEPF) * INV_STEP;
        int idx = (int)f;
        idx = max(0, min(idx, NUM_BUCKETS - 1));
        float delta = (xc - LB + STEPF) - (float)idx * STEPF;

        float2 tw = __ldg(&g_tab[u * NUM_BUCKETS + idx]);
        float logit = fmaf(delta, tw.y, tw.x);
        // sigmoid
        float e = __expf(-logit);
        oo[j] = __frcp_rn(1.0f + e);
    }

    float4 ov;
    ov.x = oo[0]; ov.y = oo[1]; ov.z = oo[2]; ov.w = oo[3];
    out4[i] = ov;
}

// ---------------------------------------------------------------------------
extern "C" void kernel_launch(void* const* d_in, const int* in_sizes, int n_in,
                              void* d_out, int out_size) {
    const float* x = (const float*)d_in[0];   // (65536, 256)
    const float* v = (const float*)d_in[1];   // (256, 501)
    const float* b = (const float*)d_in[2];   // (256,)
    float* out = (float*)d_out;

    // Build the (unit, bucket) table
    build_table_kernel<<<UNITS, 512>>>(v, b);

    // Main elementwise pass
    const int total = in_sizes[0];            // 65536*256
    const int nvec = total / 4;
    const int threads = 256;
    const int blocks = (nvec + threads - 1) / threads;
    iso_main_kernel<<<blocks, threads>>>((const float4*)x, (float4*)out, nvec);
}